// round 8
// baseline (speedup 1.0000x reference)
#include <cuda_runtime.h>
#include <math.h>

#define NQ 20
#define NSTATE (1 << NQ)

typedef unsigned long long u64;

__device__ __align__(16) float2 d_state[NSTATE];
__device__ float d_partial[512];

// ---------- packed f32x2 helpers ----------
__device__ __forceinline__ u64 pack2(float lo, float hi) {
    u64 d; asm("mov.b64 %0,{%1,%2};" : "=l"(d) : "f"(lo), "f"(hi)); return d;
}
__device__ __forceinline__ u64 swp(u64 x) {
    u64 d;
    asm("{\n\t.reg .b32 lo,hi;\n\tmov.b64 {lo,hi}, %1;\n\tmov.b64 %0,{hi,lo};\n\t}"
        : "=l"(d) : "l"(x));
    return d;
}
__device__ __forceinline__ u64 mul2(u64 a, u64 b) {
    u64 d; asm("mul.rn.f32x2 %0,%1,%2;" : "=l"(d) : "l"(a), "l"(b)); return d;
}
__device__ __forceinline__ u64 fma2(u64 a, u64 b, u64 c) {
    u64 d; asm("fma.rn.f32x2 %0,%1,%2,%3;" : "=l"(d) : "l"(a), "l"(b), "l"(c)); return d;
}
__device__ __forceinline__ float2 unp(u64 x) {
    float2 f; asm("mov.b64 {%0,%1}, %2;" : "=f"(f.x), "=f"(f.y) : "l"(x)); return f;
}
__device__ __forceinline__ float tanh_ap(float x) {
    float y; asm("tanh.approx.f32 %0,%1;" : "=f"(y) : "f"(x)); return y;
}

// gate packed layout: [axx, bxx, bxy, cxx, cxy, dxx, dxy] (stride 8 in smem)
__device__ __forceinline__ void make_gate_packed(const float* p, u64* dst) {
    float st, ct, sl, cl, sp, cp;
    sincosf(0.5f * p[0], &st, &ct);
    sincosf(p[2], &sl, &cl);
    sincosf(p[1], &sp, &cp);
    float bx = -cl * st, by = -sl * st;
    float cx = cp * st, cy = sp * st;
    float cpl = cp * cl - sp * sl, spl = sp * cl + cp * sl;
    float dx = cpl * ct, dy = spl * ct;
    dst[0] = pack2(ct, ct);
    dst[1] = pack2(bx, bx);
    dst[2] = pack2(-by, by);
    dst[3] = pack2(cx, cx);
    dst[4] = pack2(-cy, cy);
    dst[5] = pack2(dx, dx);
    dst[6] = pack2(-dy, dy);
}

// n0 = a*x0 + b*x1 (a real), n1 = c*x0 + d*x1, complex, packed re/im in u64
__device__ __forceinline__ void cpair(const u64* g, u64& x0, u64& x1) {
    u64 x0s = swp(x0), x1s = swp(x1);
    u64 n0 = mul2(g[0], x0);
    n0 = fma2(g[1], x1, n0);
    n0 = fma2(g[2], x1s, n0);
    u64 n1 = mul2(g[3], x0);
    n1 = fma2(g[4], x0s, n1);
    n1 = fma2(g[5], x1, n1);
    n1 = fma2(g[6], x1s, n1);
    x0 = n0; x1 = n1;
}

// 8-amp register window (3 bits). J in {0,1,2}.
template <int J>
__device__ __forceinline__ void u3_reg(u64* v, const u64* sgate) {
    u64 g[7];
#pragma unroll
    for (int i = 0; i < 7; i++) g[i] = sgate[i];
#pragma unroll
    for (int p = 0; p < 4; p++) {
        int x = p & ((1 << J) - 1);
        int i0 = ((p ^ x) << 1) | x;
        cpair(g, v[i0], v[i0 | (1 << J)]);
    }
}

template <int C, int T>
__device__ __forceinline__ void cu3_reg(u64* v, const u64* sgate) {
    u64 g[7];
#pragma unroll
    for (int i = 0; i < 7; i++) g[i] = sgate[i];
    constexpr int B1 = (C < T) ? C : T;
    constexpr int B2 = (C < T) ? T : C;
#pragma unroll
    for (int p = 0; p < 2; p++) {
        int x = p & ((1 << B1) - 1);
        int t1 = ((p ^ x) << 1) | x;
        int y = t1 & ((1 << B2) - 1);
        int i0 = (((t1 ^ y) << 1) | y) | (1 << C);
        cpair(g, v[i0], v[i0 | (1 << T)]);
    }
}

// Swizzle for the 2048-entry u64 tile:
//   bit4 -> pos1, bit5 -> pos2, bit6 -> pos0^pos3  (involutive bijection)
__device__ __forceinline__ int sw(int i) {
    return i ^ (((i >> 4) & 1) << 1) ^ (((i >> 5) & 1) << 2) ^ (((i >> 6) & 1) * 9);
}

// layout with window base bit B: local index = (t low B bits) | (r << B) | (t high << (B+3))
template <int B>
__device__ __forceinline__ int lidx(int t, int r) {
    int lo = t & ((1 << B) - 1);
    return lo | (r << B) | ((t >> B) << (B + 3));
}

template <int B1, int B2, bool PRESYNC>
__device__ __forceinline__ void trans(u64* v, u64* tile, int t) {
    if (PRESYNC) __syncthreads();
#pragma unroll
    for (int r = 0; r < 8; r++) tile[sw(lidx<B1>(t, r))] = v[r];
    __syncthreads();
#pragma unroll
    for (int r = 0; r < 8; r++) v[r] = tile[sw(lidx<B2>(t, r))];
}

// gate schedule tables: type (0=u3, 1=cu3) and parameter index
__device__ const unsigned char K1_type[21] = {0,0,0,1,1, 0,0,1,1, 0,0,1,1, 0,0,1,1, 0,0,1,1};
__device__ const unsigned char K1_idx[21]  = {0,1,2,0,1, 3,4,2,3, 5,6,4,5, 7,8,6,7, 9,10,8,9};
__device__ const unsigned char K2_type[19] = {0,0,1,1, 0,0,1,1, 0,0,1,1, 0,0,1,1, 0,1,1};
__device__ const unsigned char K2_idx[19]  = {11,12,10,11, 13,14,12,13, 15,16,14,15, 17,18,16,17, 19,18,19};

// ============================================================================
// K1 body: local bits = g0..g10; enters w1 (B=0: v[r] = bits 0..2), exits B=8.
// Gates: U3 q0..10, CU3 (0,1)..(9,10). 5 windows, 4 transposes.
// ============================================================================
__device__ __forceinline__ void K1_body(u64* v, u64* tile, const u64* sg, int t) {
    u3_reg<0>(v, sg + 0 * 8); u3_reg<1>(v, sg + 1 * 8); u3_reg<2>(v, sg + 2 * 8);
    cu3_reg<0, 1>(v, sg + 3 * 8); cu3_reg<1, 2>(v, sg + 4 * 8);
    trans<0, 2, false>(v, tile, t);
    u3_reg<1>(v, sg + 5 * 8); u3_reg<2>(v, sg + 6 * 8);
    cu3_reg<0, 1>(v, sg + 7 * 8); cu3_reg<1, 2>(v, sg + 8 * 8);
    trans<2, 4, true>(v, tile, t);
    u3_reg<1>(v, sg + 9 * 8); u3_reg<2>(v, sg + 10 * 8);
    cu3_reg<0, 1>(v, sg + 11 * 8); cu3_reg<1, 2>(v, sg + 12 * 8);
    trans<4, 6, true>(v, tile, t);
    u3_reg<1>(v, sg + 13 * 8); u3_reg<2>(v, sg + 14 * 8);
    cu3_reg<0, 1>(v, sg + 15 * 8); cu3_reg<1, 2>(v, sg + 16 * 8);
    trans<6, 8, true>(v, tile, t);
    u3_reg<1>(v, sg + 17 * 8); u3_reg<2>(v, sg + 18 * 8);
    cu3_reg<0, 1>(v, sg + 19 * 8); cu3_reg<1, 2>(v, sg + 20 * 8);
}

// ============================================================================
// K2 body: local l0..l9 = g10..g19, l10 = g0; enters w1 (B=0), exits B=8.
// Gates: U3 q11..19, CU3 (10,11)..(18,19),(19,0). 5 windows, 4 transposes.
// ============================================================================
template <bool PRESYNC>
__device__ __forceinline__ void K2_body(u64* v, u64* tile, const u64* sg, int t) {
    u3_reg<1>(v, sg + 0 * 8); u3_reg<2>(v, sg + 1 * 8);
    cu3_reg<0, 1>(v, sg + 2 * 8); cu3_reg<1, 2>(v, sg + 3 * 8);
    trans<0, 2, PRESYNC>(v, tile, t);
    u3_reg<1>(v, sg + 4 * 8); u3_reg<2>(v, sg + 5 * 8);
    cu3_reg<0, 1>(v, sg + 6 * 8); cu3_reg<1, 2>(v, sg + 7 * 8);
    trans<2, 4, true>(v, tile, t);
    u3_reg<1>(v, sg + 8 * 8); u3_reg<2>(v, sg + 9 * 8);
    cu3_reg<0, 1>(v, sg + 10 * 8); cu3_reg<1, 2>(v, sg + 11 * 8);
    trans<4, 6, true>(v, tile, t);
    u3_reg<1>(v, sg + 12 * 8); u3_reg<2>(v, sg + 13 * 8);
    cu3_reg<0, 1>(v, sg + 14 * 8); cu3_reg<1, 2>(v, sg + 15 * 8);
    trans<6, 8, true>(v, tile, t);
    u3_reg<1>(v, sg + 16 * 8);
    cu3_reg<0, 1>(v, sg + 17 * 8); cu3_reg<1, 2>(v, sg + 18 * 8);
}

// K2 exit-layout store: v[r] pairs with v[r|4] (differ in g0) -> 16B stores.
// g = r2 | (cta<<1) | (tid<<10) | (r0<<18) | (r1<<19)
__device__ __forceinline__ void K2_store(const u64* v, u64* ds, int tid, int cta) {
#pragma unroll
    for (int r = 0; r < 4; r++) {
        int g = (cta << 1) | (tid << 10) | ((r & 1) << 18) | (((r >> 1) & 1) << 19);
        ulonglong2 w; w.x = v[r]; w.y = v[r | 4];
        *reinterpret_cast<ulonglong2*>(ds + g) = w;
    }
}

// ============================================================================
// Fused K1(0)+K2(0): after K1(0) from |0..0>, only the 2048 amps with
// g11..g19 = 0 are nonzero. Every CTA computes that tile redundantly, extracts
// its 2 needed amps, runs K2(0).
// ============================================================================
__global__ void __launch_bounds__(256, 4) gate_AB0(const float* __restrict__ u3p,
                                                   const float* __restrict__ cu3p) {
    __shared__ u64 tile[2048];
    __shared__ u64 sg[40 * 8];
    int tid = threadIdx.x, cta = blockIdx.x;

    if (tid < 40) {
        const float* p;
        if (tid < 21) p = K1_type[tid] ? cu3p + K1_idx[tid] * 3 : u3p + K1_idx[tid] * 3;
        else {
            int s = tid - 21;
            p = K2_type[s] ? cu3p + K2_idx[s] * 3 : u3p + K2_idx[s] * 3;
        }
        make_gate_packed(p, sg + tid * 8);
    }

    u64 v[8];
#pragma unroll
    for (int r = 0; r < 8; r++) v[r] = 0ull;
    if (tid == 0) v[0] = pack2(1.f, 0.f);  // |0..0> in w1 layout
    __syncthreads();

    K1_body(v, tile, sg, tid);

    // write K1(0) tile at canonical local index (B=8 layout: l = tid | (r<<8))
#pragma unroll
    for (int r = 0; r < 8; r++) tile[sw(tid | (r << 8))] = v[r];
    __syncthreads();

    // K2 w1 nonzero inputs: K2-local l3..l9 = g13..g19 = tid bits 0..6 (must be 0),
    // l10 = g0 = tid bit 7; tile index = g0 | (g1..g9 = cta)<<1 | (g10 = r)<<10.
    u64 a0 = 0ull, a1 = 0ull;
    if ((tid & 127) == 0) {
        int b = (tid >> 7) | (cta << 1);
        a0 = tile[sw(b)];          // g10 = 0
        a1 = tile[sw(b | 1024)];   // g10 = 1
    }
#pragma unroll
    for (int r = 0; r < 8; r++) v[r] = 0ull;
    v[0] = a0; v[1] = a1;

    K2_body<true>(v, tile, sg + 21 * 8, tid);
    K2_store(v, (u64*)d_state, tid, cta);
}

// ============================================================================
// K1 (k=1,2): coalesced load (64B/thread) & store; canonical state layout.
// ============================================================================
__global__ void __launch_bounds__(256, 4) gate_K1(const float* __restrict__ u3p,
                                                  const float* __restrict__ cu3p, int k) {
    __shared__ u64 tile[2048];
    __shared__ u64 sg[21 * 8];
    int tid = threadIdx.x, cta = blockIdx.x;
    u64* gp = (u64*)d_state + ((size_t)cta << 11);

    if (tid < 21) {
        int q = k * NQ + K1_idx[tid];
        const float* p = K1_type[tid] ? cu3p + q * 3 : u3p + q * 3;
        make_gate_packed(p, sg + tid * 8);
    }

    u64 v[8];
    const ulonglong2* g2 = (const ulonglong2*)gp;
#pragma unroll
    for (int j = 0; j < 4; j++) {  // v[r] = gp[(tid<<3)|r]
        ulonglong2 w = g2[tid * 4 + j];
        v[2 * j] = w.x; v[2 * j + 1] = w.y;
    }
    __syncthreads();

    K1_body(v, tile, sg, tid);

#pragma unroll
    for (int r = 0; r < 8; r++) gp[tid | (r << 8)] = v[r];
}

// ============================================================================
// K2 (k=1,2): cta = g1..9. Load: g = (tid>>7)|(cta<<1)|(r<<10)|((tid&127)<<13).
// LAST fuses the pointwise finalize + bit-reversed output + partial sums.
// ============================================================================
template <bool LAST>
__global__ void __launch_bounds__(256, 4) gate_K2(const float* __restrict__ u3p,
                                                  const float* __restrict__ cu3p, int k,
                                                  float* __restrict__ out) {
    __shared__ u64 tile[2048];
    __shared__ u64 sg[19 * 8];
    int tid = threadIdx.x, cta = blockIdx.x;

    if (tid < 19) {
        int q = k * NQ + K2_idx[tid];
        const float* p = K2_type[tid] ? cu3p + q * 3 : u3p + q * 3;
        make_gate_packed(p, sg + tid * 8);
    }

    u64* ds = (u64*)d_state;
    int b0 = (tid >> 7) | (cta << 1) | ((tid & 127) << 13);
    u64 v[8];
#pragma unroll
    for (int r = 0; r < 8; r++) v[r] = ds[b0 | (r << 10)];
    __syncthreads();

    K2_body<false>(v, tile, sg, tid);

    if (!LAST) {
        K2_store(v, ds, tid, cta);
    } else {
        // exit layout: g = r2 | (cta<<1) | (tid<<10) | (r0<<18) | (r1<<19)
        // out_idx = brev20(g) = (r2<<19) | (rev9(cta)<<10) | (rev8(tid)<<2) | (r0<<1) | r1
        float xv[8];
        float sum = 0.f;
#pragma unroll
        for (int r = 0; r < 8; r++) {
            float2 a = unp(v[r]);
            float pr = a.x * a.x + a.y * a.y;
            float t = 0.8f * tanh_ap(52428.8f * pr);  // gamma * 2^19
            xv[r] = __powf(t, 0.3f);
            sum += xv[r];
        }
        int base = ((int)(__brev((unsigned)cta) >> 23) << 10) |
                   ((int)(__brev((unsigned)tid) >> 24) << 2);
        *(float4*)(out + base) = make_float4(xv[0], xv[2], xv[1], xv[3]);
        *(float4*)(out + (base | (1 << 19))) = make_float4(xv[4], xv[6], xv[5], xv[7]);

        for (int o = 16; o > 0; o >>= 1) sum += __shfl_down_sync(0xffffffffu, sum, o);
        __shared__ float red[8];
        if ((tid & 31) == 0) red[tid >> 5] = sum;
        __syncthreads();
        if (tid == 0) {
            float s = 0.f;
#pragma unroll
            for (int w = 0; w < 8; w++) s += red[w];
            d_partial[cta] = s;
        }
    }
}

// mean from 512 partials (redundant per CTA, L2-hot), then subtract
__global__ void __launch_bounds__(256) finalize_sub(float4* __restrict__ o4) {
    int tid = threadIdx.x;
    int i = blockIdx.x * 256 + tid;
    float4 x = o4[i];

    float s = d_partial[tid] + d_partial[tid + 256];
    for (int o = 16; o > 0; o >>= 1) s += __shfl_down_sync(0xffffffffu, s, o);
    __shared__ float red[8];
    __shared__ float mean;
    if ((tid & 31) == 0) red[tid >> 5] = s;
    __syncthreads();
    if (tid == 0) {
        float t = 0.f;
#pragma unroll
        for (int w = 0; w < 8; w++) t += red[w];
        mean = t * (1.0f / 1048576.0f);
    }
    __syncthreads();
    float m = mean;
    x.x -= m; x.y -= m; x.z -= m; x.w -= m;
    o4[i] = x;
}

extern "C" void kernel_launch(void* const* d_in, const int* in_sizes, int n_in,
                              void* d_out, int out_size) {
    const float* u3p = (const float*)d_in[0];   // (3, 20, 3)
    const float* cu3p = (const float*)d_in[1];  // (3, 20, 3)
    float* out = (float*)d_out;                 // 2^20 floats

    gate_AB0<<<512, 256>>>(u3p, cu3p);
    gate_K1<<<512, 256>>>(u3p, cu3p, 1);
    gate_K2<false><<<512, 256>>>(u3p, cu3p, 1, out);
    gate_K1<<<512, 256>>>(u3p, cu3p, 2);
    gate_K2<true><<<512, 256>>>(u3p, cu3p, 2, out);
    finalize_sub<<<1024, 256>>>((float4*)out);
}